// round 3
// baseline (speedup 1.0000x reference)
#include <cuda_runtime.h>

// Problem constants (fixed by the dataset): B=256, T=512, K=128
#define Bn 256
#define Tn 512
#define Kn 128

// Per-batch partial results (log_z - score). Device global scratch: no allocs.
__device__ float g_partial[Bn];

// ---- packed f32x2 helpers (sm_103a FFMA2) ---------------------------------
__device__ __forceinline__ unsigned long long fma2(unsigned long long a,
                                                   unsigned long long b,
                                                   unsigned long long c) {
    unsigned long long d;
    asm("fma.rn.f32x2 %0, %1, %2, %3;" : "=l"(d) : "l"(a), "l"(b), "l"(c));
    return d;
}
__device__ __forceinline__ unsigned long long pack2(float lo, float hi) {
    unsigned long long d;
    asm("mov.b64 %0, {%1, %2};" : "=l"(d) : "f"(lo), "f"(hi));
    return d;
}
__device__ __forceinline__ float2 unpack2(unsigned long long v) {
    float lo, hi;
    asm("mov.b64 {%0, %1}, %2;" : "=f"(lo), "=f"(hi) : "l"(v));
    return make_float2(lo, hi);
}

// One CTA per batch, 128 threads. Thread j owns alpha[j] in a register and
// the full expT[:, j] column as 64 packed f32x2 register pairs.
// Per scan step: 1 exp, 1 smem store, 1 barrier, 32 LDS.128 (broadcast),
// 64 FFMA2, 1 log. Shift for LSE stability is a stale-by-one broadcast of
// alpha[0] (exactness of LSE does not depend on the shift; only overflow does,
// and the worst-case exponent arg is ~28 << 88).
__global__ __launch_bounds__(128, 2) void crf_forward_kernel(
    const float* __restrict__ logits,   // [B, T, K]
    const int*   __restrict__ labels,   // [B, T]
    const int*   __restrict__ seq_lens, // [B]
    const float* __restrict__ trans)    // [K, K] trans[i*K + j], i=from, j=to
{
    __shared__ __align__(16) float sh_aexp[2][Kn];
    __shared__ float sh_shift[2];
    __shared__ float sh_wred[4];

    const int b    = blockIdx.x;
    const int j    = threadIdx.x;        // 0..127
    const int lane = j & 31;
    const int warp = j >> 5;

    const int    Tlen = seq_lens[b];     // 1..512
    const float* lg   = logits + (size_t)b * Tn * Kn;
    const int*   lb   = labels + b * Tn;

    // ---------------- gold-path score: unary + pairwise ----------------
    float sc = 0.f;
    for (int t = j; t < Tlen; t += Kn) {
        int y = lb[t];
        sc += lg[t * Kn + y];
        if (t >= 1) sc += trans[lb[t - 1] * Kn + y];
    }
    #pragma unroll
    for (int o = 16; o; o >>= 1) sc += __shfl_xor_sync(0xffffffffu, sc, o);
    if (lane == 0) sh_wred[warp] = sc;

    // ---------------- expT column j, packed over i-pairs ----------------
    unsigned long long eT2[64];
    #pragma unroll
    for (int k = 0; k < 64; k++) {
        float e0 = __expf(trans[(2 * k)     * Kn + j]);   // coalesced in j
        float e1 = __expf(trans[(2 * k + 1) * Kn + j]);
        eT2[k] = pack2(e0, e1);
    }

    float alpha   = lg[j];          // alpha_0
    float shift   = 0.f;            // first-step shift; alpha_0 ~ N(0,1)
    float lo_next = lg[Kn + j];     // prefetch t=1 (T rows fully allocated)

    __syncthreads();
    const float score = (sh_wred[0] + sh_wred[1]) + (sh_wred[2] + sh_wred[3]);

    // ---------------- forward recursion (only unmasked steps) -----------
    int buf = 0;
    for (int t = 1; t < Tlen; t++) {
        float lo = lo_next;
        int   tn = (t + 1 < Tn) ? (t + 1) : t;
        lo_next  = lg[tn * Kn + j];

        sh_aexp[buf][j] = __expf(alpha - shift);
        if (j == 0) sh_shift[buf] = alpha;     // publish next shift
        __syncthreads();                       // the ONLY barrier per step
        const float nshift = sh_shift[buf];

        // s_j = sum_i aexp[i] * expT[i][j]  -- 64 packed FMAs, 4 chains
        const double2* ap = (const double2*)sh_aexp[buf];
        unsigned long long a0 = 0ull, a1 = 0ull, a2 = 0ull, a3 = 0ull;
        #pragma unroll
        for (int k = 0; k < 16; k++) {
            double2 x = ap[2 * k];             // LDS.128 broadcast
            double2 y = ap[2 * k + 1];
            a0 = fma2(__double_as_longlong(x.x), eT2[4 * k + 0], a0);
            a1 = fma2(__double_as_longlong(x.y), eT2[4 * k + 1], a1);
            a2 = fma2(__double_as_longlong(y.x), eT2[4 * k + 2], a2);
            a3 = fma2(__double_as_longlong(y.y), eT2[4 * k + 3], a3);
        }
        float2 p0 = unpack2(a0), p1 = unpack2(a1);
        float2 p2 = unpack2(a2), p3 = unpack2(a3);
        float s = ((p0.x + p0.y) + (p1.x + p1.y))
                + ((p2.x + p2.y) + (p3.x + p3.y));

        alpha = shift + __logf(s) + lo;
        shift = nshift;
        buf ^= 1;
    }

    // ---------------- log_z = LSE(alpha_final) --------------------------
    __syncthreads();                           // protect sh_wred reuse
    float v = alpha;
    #pragma unroll
    for (int o = 16; o; o >>= 1) v = fmaxf(v, __shfl_xor_sync(0xffffffffu, v, o));
    if (lane == 0) sh_wred[warp] = v;
    __syncthreads();
    const float m = fmaxf(fmaxf(sh_wred[0], sh_wred[1]),
                          fmaxf(sh_wred[2], sh_wred[3]));

    float e = __expf(alpha - m);
    #pragma unroll
    for (int o = 16; o; o >>= 1) e += __shfl_xor_sync(0xffffffffu, e, o);
    __syncthreads();                           // all reads of m done
    if (lane == 0) sh_wred[warp] = e;
    __syncthreads();

    if (j == 0) {
        float stot = (sh_wred[0] + sh_wred[1]) + (sh_wred[2] + sh_wred[3]);
        g_partial[b] = m + __logf(stot) - score;   // per-batch NLL
    }
}

// Deterministic final reduction: one warp, fixed tree over 256 values.
__global__ void crf_reduce_kernel(float* __restrict__ out)
{
    int lane = threadIdx.x;        // 32 threads
    float s = 0.f;
    #pragma unroll
    for (int k = 0; k < 8; k++)    // fixed order: deterministic
        s += g_partial[lane + 32 * k];
    #pragma unroll
    for (int o = 16; o; o >>= 1) s += __shfl_xor_sync(0xffffffffu, s, o);
    if (lane == 0) out[0] = s;
}

extern "C" void kernel_launch(void* const* d_in, const int* in_sizes, int n_in,
                              void* d_out, int out_size)
{
    const float* logits   = (const float*)d_in[0];
    const int*   labels   = (const int*)  d_in[1];
    const int*   seq_lens = (const int*)  d_in[2];
    const float* trans    = (const float*)d_in[3];
    float*       out      = (float*)d_out;

    crf_forward_kernel<<<Bn, 128>>>(logits, labels, seq_lens, trans);
    crf_reduce_kernel<<<1, 32>>>(out);
}

// round 4
// speedup vs baseline: 1.0303x; 1.0303x over previous
#include <cuda_runtime.h>

// Problem constants (fixed by the dataset): B=256, T=512, K=128
#define Bn 256
#define Tn 512
#define Kn 128
#define PD 4          // logit prefetch ring depth (PD*step_cyc > DRAM latency)

// Device scratch (no allocs allowed).
__device__ float g_partial[Bn];
__device__ int   g_perm[Bn];      // g_perm[rank] = batch index, by seq_len

// ---- packed f32x2 helpers (sm_103a FFMA2) ---------------------------------
__device__ __forceinline__ unsigned long long fma2(unsigned long long a,
                                                   unsigned long long b,
                                                   unsigned long long c) {
    unsigned long long d;
    asm("fma.rn.f32x2 %0, %1, %2, %3;" : "=l"(d) : "l"(a), "l"(b), "l"(c));
    return d;
}
__device__ __forceinline__ unsigned long long pack2(float lo, float hi) {
    unsigned long long d;
    asm("mov.b64 %0, {%1, %2};" : "=l"(d) : "f"(lo), "f"(hi));
    return d;
}
__device__ __forceinline__ float2 unpack2(unsigned long long v) {
    float lo, hi;
    asm("mov.b64 {%0, %1}, %2;" : "=f"(lo), "=f"(hi) : "l"(v));
    return make_float2(lo, hi);
}

// ---- scheduler: rank batches by seq_len (deterministic, O(B^2)) -----------
__global__ void crf_sched_kernel(const int* __restrict__ seq_lens)
{
    __shared__ int L[Bn];
    const int i = threadIdx.x;            // 256 threads
    L[i] = seq_lens[i];
    __syncthreads();
    const int li = L[i];
    int r = 0;
    #pragma unroll 8
    for (int k = 0; k < Bn; k++) {
        int lk = L[k];
        r += (lk < li) || (lk == li && k < i);   // unique ranks
    }
    g_perm[r] = i;
}

// ---- forward kernel: grid=128 CTAs, 128 threads, one CTA per SM ----------
// CTA c sequentially processes batches perm[c] and perm[255-c] (length-
// balanced pairs: sums concentrate near T+1, so makespan ~= mean, and no CTA
// shares an SM -> full issue bandwidth for the scan's critical path).
// Thread j owns alpha[j] and the full expT[:, j] column as 64 packed f32x2
// registers (shared across both batches). Per step: 1 exp, 1 STS, 1 barrier,
// 32 LDS.128 broadcast, 64 FFMA2, 1 log. LSE shift is stale-by-one alpha[0].
__global__ __launch_bounds__(128, 1) void crf_forward_kernel(
    const float* __restrict__ logits,   // [B, T, K]
    const int*   __restrict__ labels,   // [B, T]
    const int*   __restrict__ seq_lens, // [B]
    const float* __restrict__ trans)    // [K, K] trans[i*K + j]
{
    __shared__ __align__(16) float sh_aexp[2][Kn];
    __shared__ float sh_shift[2];
    __shared__ float sh_wred[4];

    const int c    = blockIdx.x;         // 0..127
    const int j    = threadIdx.x;        // 0..127
    const int lane = j & 31;
    const int warp = j >> 5;

    // expT column j, packed over i-pairs (reused for both batches)
    unsigned long long eT2[64];
    #pragma unroll
    for (int k = 0; k < 64; k++) {
        float e0 = __expf(trans[(2 * k)     * Kn + j]);   // coalesced in j
        float e1 = __expf(trans[(2 * k + 1) * Kn + j]);
        eT2[k] = pack2(e0, e1);
    }

    for (int p = 0; p < 2; p++) {
        const int b = g_perm[p == 0 ? c : (Bn - 1 - c)];
        const int    Tlen = seq_lens[b];                  // 1..512
        const float* lg   = logits + (size_t)b * Tn * Kn;
        const int*   lb   = labels + b * Tn;

        // ---------- gold-path score: unary + pairwise ----------
        float sc = 0.f;
        for (int t = j; t < Tlen; t += Kn) {
            int y = lb[t];
            sc += lg[t * Kn + y];
            if (t >= 1) sc += trans[lb[t - 1] * Kn + y];
        }
        #pragma unroll
        for (int o = 16; o; o >>= 1) sc += __shfl_xor_sync(0xffffffffu, sc, o);
        if (lane == 0) sh_wred[warp] = sc;

        float alpha = lg[j];                 // alpha_0
        float shift = 0.f;                   // alpha_0 ~ N(0,1): safe shift

        // prefetch ring: lo_buf[(t-1) & 3] holds logits row t
        float lo_buf[PD];
        #pragma unroll
        for (int i = 0; i < PD; i++) {
            int idx = (1 + i < Tn) ? (1 + i) : (Tn - 1);
            lo_buf[i] = lg[idx * Kn + j];
        }

        __syncthreads();
        const float score = (sh_wred[0] + sh_wred[1]) + (sh_wred[2] + sh_wred[3]);
        __syncthreads();                     // sh_wred free for reuse below

        // ---------- forward recursion (only unmasked steps) ----------
        int buf = 0;
        for (int t = 1; t < Tlen; t++) {
            const int slot = (t - 1) & (PD - 1);
            const float lo = lo_buf[slot];
            int idx = (t + PD < Tn) ? (t + PD) : (Tn - 1);
            lo_buf[slot] = lg[idx * Kn + j];          // refill for step t+PD

            sh_aexp[buf][j] = __expf(alpha - shift);
            if (j == 0) sh_shift[buf] = alpha;        // publish next shift
            __syncthreads();                          // the ONLY barrier/step
            const float nshift = sh_shift[buf];

            // s_j = sum_i aexp[i] * expT[i][j] : 64 packed FMAs, 4 chains
            const double2* ap = (const double2*)sh_aexp[buf];
            unsigned long long a0 = 0ull, a1 = 0ull, a2 = 0ull, a3 = 0ull;
            #pragma unroll
            for (int k = 0; k < 16; k++) {
                double2 x = ap[2 * k];                // LDS.128 broadcast
                double2 y = ap[2 * k + 1];
                a0 = fma2(__double_as_longlong(x.x), eT2[4 * k + 0], a0);
                a1 = fma2(__double_as_longlong(x.y), eT2[4 * k + 1], a1);
                a2 = fma2(__double_as_longlong(y.x), eT2[4 * k + 2], a2);
                a3 = fma2(__double_as_longlong(y.y), eT2[4 * k + 3], a3);
            }
            float2 p0 = unpack2(a0), p1 = unpack2(a1);
            float2 p2 = unpack2(a2), p3 = unpack2(a3);
            float s = ((p0.x + p0.y) + (p1.x + p1.y))
                    + ((p2.x + p2.y) + (p3.x + p3.y));

            alpha = shift + __logf(s) + lo;
            shift = nshift;
            buf ^= 1;
        }

        // ---------- log_z = LSE(alpha_final) ----------
        float v = alpha;
        #pragma unroll
        for (int o = 16; o; o >>= 1)
            v = fmaxf(v, __shfl_xor_sync(0xffffffffu, v, o));
        if (lane == 0) sh_wred[warp] = v;
        __syncthreads();
        const float m = fmaxf(fmaxf(sh_wred[0], sh_wred[1]),
                              fmaxf(sh_wred[2], sh_wred[3]));

        float e = __expf(alpha - m);
        #pragma unroll
        for (int o = 16; o; o >>= 1) e += __shfl_xor_sync(0xffffffffu, e, o);
        __syncthreads();                    // all reads of m done
        if (lane == 0) sh_wred[warp] = e;
        __syncthreads();

        if (j == 0) {
            float stot = (sh_wred[0] + sh_wred[1]) + (sh_wred[2] + sh_wred[3]);
            g_partial[b] = m + __logf(stot) - score;   // per-batch NLL
        }
        __syncthreads();                    // smem safe for next batch
    }
}

// Deterministic final reduction: one warp, fixed tree over 256 values.
__global__ void crf_reduce_kernel(float* __restrict__ out)
{
    int lane = threadIdx.x;                 // 32 threads
    float s = 0.f;
    #pragma unroll
    for (int k = 0; k < 8; k++)             // fixed order: deterministic
        s += g_partial[lane + 32 * k];
    #pragma unroll
    for (int o = 16; o; o >>= 1) s += __shfl_xor_sync(0xffffffffu, s, o);
    if (lane == 0) out[0] = s;
}

extern "C" void kernel_launch(void* const* d_in, const int* in_sizes, int n_in,
                              void* d_out, int out_size)
{
    const float* logits   = (const float*)d_in[0];
    const int*   labels   = (const int*)  d_in[1];
    const int*   seq_lens = (const int*)  d_in[2];
    const float* trans    = (const float*)d_in[3];
    float*       out      = (float*)d_out;

    crf_sched_kernel<<<1, Bn>>>(seq_lens);
    crf_forward_kernel<<<Bn / 2, Kn>>>(logits, labels, seq_lens, trans);
    crf_reduce_kernel<<<1, 32>>>(out);
}

// round 5
// speedup vs baseline: 1.2100x; 1.1745x over previous
#include <cuda_runtime.h>

// Problem constants (fixed by the dataset): B=256, T=512, K=128
#define Bn 256
#define Tn 512
#define Kn 128
#define PD 4          // logit prefetch ring depth

// Device scratch (no allocs allowed).
__device__ float g_partial[Bn];
__device__ int   g_perm[Bn];      // g_perm[rank] = batch index, by seq_len

// ---- packed f32x2 helpers (sm_103a FFMA2/FADD2) ----------------------------
__device__ __forceinline__ unsigned long long fma2(unsigned long long a,
                                                   unsigned long long b,
                                                   unsigned long long c) {
    unsigned long long d;
    asm("fma.rn.f32x2 %0, %1, %2, %3;" : "=l"(d) : "l"(a), "l"(b), "l"(c));
    return d;
}
__device__ __forceinline__ unsigned long long add2(unsigned long long a,
                                                   unsigned long long b) {
    unsigned long long d;
    asm("add.rn.f32x2 %0, %1, %2;" : "=l"(d) : "l"(a), "l"(b));
    return d;
}
__device__ __forceinline__ unsigned long long pack2(float lo, float hi) {
    unsigned long long d;
    asm("mov.b64 %0, {%1, %2};" : "=l"(d) : "f"(lo), "f"(hi));
    return d;
}
__device__ __forceinline__ float2 unpack2(unsigned long long v) {
    float lo, hi;
    asm("mov.b64 {%0, %1}, %2;" : "=f"(lo), "=f"(hi) : "l"(v));
    return make_float2(lo, hi);
}

// ---- scheduler: rank batches by seq_len (deterministic, O(B^2)) -----------
__global__ void crf_sched_kernel(const int* __restrict__ seq_lens)
{
    __shared__ int L[Bn];
    const int i = threadIdx.x;            // 256 threads
    L[i] = seq_lens[i];
    __syncthreads();
    const int li = L[i];
    int r = 0;
    #pragma unroll 8
    for (int k = 0; k < Bn; k++) {
        int lk = L[k];
        r += (lk < li) || (lk == li && k < i);   // unique ranks
    }
    g_perm[r] = i;
}

// ---- forward kernel --------------------------------------------------------
// grid=128 CTAs, 256 threads, one CTA/SM. CTA c runs batches perm[c] then
// perm[255-c] (length-balanced pairs). Thread tau: column j = tau>>1, half
// h = tau&1 owns i in [64h, 64h+64) as 32 packed f32x2 registers.
// LINEAR-domain scan: smem holds beta = exp(alpha - S); per step
//   beta'_j = (sum_i beta_i expT[i][j]) * exp(lo_j - log r),  S += log r,
// with stale scale r = beta[0] (read at barrier release, so exp/log run
// concurrently with the matvec). One barrier per step; half-combine is a
// single intra-warp shuffle. Beta halves padded 68 floats apart: the pair's
// two LDS.128 broadcast addresses hit disjoint banks.
__global__ __launch_bounds__(256, 1) void crf_forward_kernel(
    const float* __restrict__ logits,   // [B, T, K]
    const int*   __restrict__ labels,   // [B, T]
    const int*   __restrict__ seq_lens, // [B]
    const float* __restrict__ trans)    // [K, K] trans[i*K + j]
{
    __shared__ __align__(16) float sh_beta[2][136]; // half0 @0, half1 @68
    __shared__ float sh_wred[8];

    const int c    = blockIdx.x;         // 0..127
    const int tau  = threadIdx.x;        // 0..255
    const int j    = tau >> 1;           // column 0..127
    const int h    = tau & 1;            // half
    const int lane = tau & 31;
    const int warp = tau >> 5;
    const int slotj = (j < 64) ? j : j + 4;   // padded beta slot for column j

    // expT rows [64h, 64h+64) of column j, packed over row-pairs
    unsigned long long eT2[32];
    #pragma unroll
    for (int k = 0; k < 32; k++) {
        float e0 = __expf(trans[(64 * h + 2 * k)     * Kn + j]);
        float e1 = __expf(trans[(64 * h + 2 * k + 1) * Kn + j]);
        eT2[k] = pack2(e0, e1);
    }

    for (int p = 0; p < 2; p++) {
        const int b = g_perm[p ? (Bn - 1 - c) : c];
        const int    Tlen = seq_lens[b];                  // 1..512
        const float* lg   = logits + (size_t)b * Tn * Kn;
        const int*   lb   = labels + b * Tn;

        // ---------- gold-path score: unary + pairwise ----------
        float sc = 0.f;
        for (int t = tau; t < Tlen; t += 256) {
            int y = lb[t];
            sc += lg[t * Kn + y];
            if (t >= 1) sc += trans[lb[t - 1] * Kn + y];
        }
        #pragma unroll
        for (int o = 16; o; o >>= 1) sc += __shfl_xor_sync(0xffffffffu, sc, o);
        if (lane == 0) sh_wred[warp] = sc;

        // beta_0 = exp(alpha_0) = exp(logits[b,0,:]), S = 0
        if (!h) sh_beta[0][slotj] = __expf(lg[j]);

        // logit prefetch ring: lo_buf[(t-1)&3] holds row t for column j
        float lo_buf[PD];
        #pragma unroll
        for (int i = 0; i < PD; i++) {
            int idx = (1 + i < Tn) ? (1 + i) : (Tn - 1);
            lo_buf[i] = lg[idx * Kn + j];
        }

        __syncthreads();
        float score = 0.f;
        #pragma unroll
        for (int w = 0; w < 8; w++) score += sh_wred[w];

        // ---------- forward recursion (only unmasked steps) ----------
        float S   = 0.f;
        int   cur = 0;
        for (int t = 1; t < Tlen; t++) {
            const int slot = (t - 1) & (PD - 1);
            const float lo = lo_buf[slot];
            int idx = (t + PD < Tn) ? (t + PD) : (Tn - 1);
            lo_buf[slot] = lg[idx * Kn + j];      // refill for step t+PD

            // stale scale: known at barrier release -> off the matvec chain
            const float r  = sh_beta[cur][0];
            const float lr = __logf(r);
            const float cj = __expf(lo - lr);
            S += lr;

            // s_j(half) = sum_{i in half} beta_i * expT[i][j]
            const double2* ap = (const double2*)(sh_beta[cur] + 68 * h);
            unsigned long long a0 = 0ull, a1 = 0ull, a2 = 0ull, a3 = 0ull;
            #pragma unroll
            for (int k = 0; k < 8; k++) {
                double2 x = ap[2 * k];            // LDS.128, 2-addr broadcast
                double2 y = ap[2 * k + 1];
                a0 = fma2(__double_as_longlong(x.x), eT2[4 * k + 0], a0);
                a1 = fma2(__double_as_longlong(x.y), eT2[4 * k + 1], a1);
                a2 = fma2(__double_as_longlong(y.x), eT2[4 * k + 2], a2);
                a3 = fma2(__double_as_longlong(y.y), eT2[4 * k + 3], a3);
            }
            unsigned long long aa = add2(add2(a0, a1), add2(a2, a3));
            float2 pp = unpack2(aa);
            float  sv = pp.x + pp.y;
            sv += __shfl_xor_sync(0xffffffffu, sv, 1);   // combine halves

            float beta = sv * cj;
            if (!h) sh_beta[cur ^ 1][slotj] = beta;
            __syncthreads();                     // the ONLY barrier per step
            cur ^= 1;
        }

        // ---------- log_z = S + log(sum_j beta_j) ----------
        __syncthreads();                         // protect sh_wred reuse
        float v = 0.f;
        if (tau < Kn) v = sh_beta[cur][(tau < 64) ? tau : tau + 4];
        #pragma unroll
        for (int o = 16; o; o >>= 1) v += __shfl_xor_sync(0xffffffffu, v, o);
        if (lane == 0) sh_wred[warp] = v;
        __syncthreads();

        if (tau == 0) {
            float stot = ((sh_wred[0] + sh_wred[1]) + (sh_wred[2] + sh_wred[3]))
                       + ((sh_wred[4] + sh_wred[5]) + (sh_wred[6] + sh_wred[7]));
            g_partial[b] = S + __logf(stot) - score;   // per-batch NLL
        }
        __syncthreads();                         // smem safe for next batch
    }
}

// Deterministic final reduction: one warp, fixed tree over 256 values.
__global__ void crf_reduce_kernel(float* __restrict__ out)
{
    int lane = threadIdx.x;                 // 32 threads
    float s = 0.f;
    #pragma unroll
    for (int k = 0; k < 8; k++)             // fixed order: deterministic
        s += g_partial[lane + 32 * k];
    #pragma unroll
    for (int o = 16; o; o >>= 1) s += __shfl_xor_sync(0xffffffffu, s, o);
    if (lane == 0) out[0] = s;
}

extern "C" void kernel_launch(void* const* d_in, const int* in_sizes, int n_in,
                              void* d_out, int out_size)
{
    const float* logits   = (const float*)d_in[0];
    const int*   labels   = (const int*)  d_in[1];
    const int*   seq_lens = (const int*)  d_in[2];
    const float* trans    = (const float*)d_in[3];
    float*       out      = (float*)d_out;

    crf_sched_kernel<<<1, Bn>>>(seq_lens);
    crf_forward_kernel<<<Bn / 2, 256>>>(logits, labels, seq_lens, trans);
    crf_reduce_kernel<<<1, 32>>>(out);
}